// round 5
// baseline (speedup 1.0000x reference)
#include <cuda_runtime.h>

#define W 512
#define H 512
#define NPLANE 48          // 16 batch * 3 channels
#define TX 32
#define TY 64
#define RAD 5
#define HX (TX + 2*RAD)    // 42 halo cols
#define HY (TY + 2*RAD)    // 74 halo rows
#define HP2 45             // halo pitch in u64 (90 words: 26 mod 32 -> conflict-free)
#define IPQ 33             // intermediate pitch (ulonglong2 / f32)
#define NT 256             // 8 warps
#define NBLOCKS ((W/TX) * (H/TY) * NPLANE)   // 6144
#define NTASKS (4 * HY)    // 296 horizontal tasks

typedef unsigned long long u64;

__device__ double   g_accum;   // zero at module load; reset by last CTA each call
__device__ unsigned g_count;   // auto-wrapping completion counter

__device__ __forceinline__ u64 pack2(float a, float b) {
    u64 r; asm("mov.b64 %0, {%1,%2};" : "=l"(r) : "f"(a), "f"(b)); return r;
}
__device__ __forceinline__ void unpack2(u64 v, float& a, float& b) {
    asm("mov.b64 {%0,%1}, %2;" : "=f"(a), "=f"(b) : "l"(v));
}
__device__ __forceinline__ u64 fma2(u64 a, u64 b, u64 c) {
    u64 d; asm("fma.rn.f32x2 %0, %1, %2, %3;" : "=l"(d) : "l"(a), "l"(b), "l"(c)); return d;
}
__device__ __forceinline__ u64 mul2(u64 a, u64 b) {
    u64 d; asm("mul.rn.f32x2 %0, %1, %2;" : "=l"(d) : "l"(a), "l"(b)); return d;
}

#define GDEF constexpr float G[11] = { \
    0.00102838f, 0.00759874f, 0.03600078f, 0.10936071f, 0.21300553f, \
    0.26601174f, \
    0.21300553f, 0.10936071f, 0.03600078f, 0.00759874f, 0.00102838f }

// horizontal 11-tap strip-of-8: accumulate from u64 (x,y) halo into regs
__device__ __forceinline__ void htask(const u64* __restrict__ src,
                                      u64 (&a1)[8], u64 (&a2)[8], float (&a3)[8]) {
    GDEF;
    #pragma unroll
    for (int o = 0; o < 8; ++o) { a1[o] = 0ull; a2[o] = 0ull; a3[o] = 0.f; }
    #pragma unroll
    for (int j = 0; j < 18; ++j) {
        u64 v = src[j];
        u64 v2 = mul2(v, v);
        float xa, ya;
        unpack2(v, xa, ya);
        float p = xa * ya;
        #pragma unroll
        for (int o = 0; o < 8; ++o) {
            int k = j - o;
            if (k >= 0 && k < 11) {
                u64 gk = pack2(G[k], G[k]);
                a1[o] = fma2(v,  gk, a1[o]);
                a2[o] = fma2(v2, gk, a2[o]);
                a3[o] = fmaf(p, G[k], a3[o]);
            }
        }
    }
}

__global__ __launch_bounds__(NT, 4) void ssim_main(const float* __restrict__ X,
                                                   const float* __restrict__ Y,
                                                   float* __restrict__ out) {
    extern __shared__ u64 sm[];
    // Region layout (48,840 B total):
    //   s_q  : ulonglong2[HY*IPQ]  @ 0      .. 39,072   ((hx,hy),(hx2,hy2))
    //   s_xy : float[HY*IPQ]       @ 39,072 .. 48,840   (hxy)
    //   s_halo (u64[HY*HP2], 26,640 B) ALIASES s_q[0..]; dead after store-barrier.
    ulonglong2* s_q  = (ulonglong2*)sm;
    float*      s_xy = (float*)(s_q + HY * IPQ);
    u64*        s_halo = sm;

    const int tid = threadIdx.x;
    const int x0 = blockIdx.x * TX - RAD;
    const int y0 = blockIdx.y * TY - RAD;
    const float* Xp = X + (size_t)blockIdx.z * (W * H);
    const float* Yp = Y + (size_t)blockIdx.z * (W * H);

    // ---- Phase A: load (x,y) halo as packed u64, pitch 45 ----
    const bool interior = (x0 >= 0) & (y0 >= 0) & (x0 + HX <= W) & (y0 + HY <= H);
    if (interior) {
        for (int i = tid; i < HY * HX; i += NT) {
            int rr = i / HX;
            int cc = i - rr * HX;
            int idx = (y0 + rr) * W + (x0 + cc);
            s_halo[rr * HP2 + cc] = pack2(Xp[idx], Yp[idx]);
        }
    } else {
        for (int i = tid; i < HY * HX; i += NT) {
            int rr = i / HX;
            int cc = i - rr * HX;
            int gx = x0 + cc, gy = y0 + rr;
            float xv = 0.f, yv = 0.f;
            if ((unsigned)gx < (unsigned)W && (unsigned)gy < (unsigned)H) {
                int idx = gy * W + gx;
                xv = Xp[idx];
                yv = Yp[idx];
            }
            s_halo[rr * HP2 + cc] = pack2(xv, yv);
        }
    }
    __syncthreads();

    // ---- Phase B: horizontal conv. Task t: row = t>>2, strip c0 = (t&3)*8 ----
    // Round 2 first (t in [256,296): rows 64..73). Their float4 stores land at
    // bytes >= 64*528 = 33,792 > halo end (26,640) -> safe to store immediately.
    {
        int t2 = tid + NT;
        if (t2 < NTASKS) {
            int r  = t2 >> 2;
            int c0 = (t2 & 3) << 3;
            u64 a1[8], a2[8]; float a3[8];
            htask(s_halo + r * HP2 + c0, a1, a2, a3);
            ulonglong2* dq = s_q  + r * IPQ + c0;
            float*      d3 = s_xy + r * IPQ + c0;
            #pragma unroll
            for (int o = 0; o < 8; ++o) {
                dq[o] = make_ulonglong2(a1[o], a2[o]);
                d3[o] = a3[o];
            }
        }
    }
    // Round 1 (rows 0..63): accumulate into regs; xy plane (offset >= 39,072)
    // is outside the halo so it stores now; float4 stores defer past barrier.
    u64 b1[8], b2[8];
    {
        int r  = tid >> 2;
        int c0 = (tid & 3) << 3;
        float a3[8];
        htask(s_halo + r * HP2 + c0, b1, b2, a3);
        float* d3 = s_xy + r * IPQ + c0;
        #pragma unroll
        for (int o = 0; o < 8; ++o) d3[o] = a3[o];
    }
    __syncthreads();      // all halo reads complete; safe to overwrite alias
    {
        int r  = tid >> 2;
        int c0 = (tid & 3) << 3;
        ulonglong2* dq = s_q + r * IPQ + c0;
        #pragma unroll
        for (int o = 0; o < 8; ++o) dq[o] = make_ulonglong2(b1[o], b2[o]);
    }
    __syncthreads();

    // ---- Phase C: vertical conv, 8 warps x 8-row strips (exactly 64 rows) ----
    float lsum = 0.f;
    {
        GDEF;
        const int col = tid & 31;
        const int r0  = (tid >> 5) << 3;
        u64 a1[8], a2[8]; float a3[8];
        #pragma unroll
        for (int o = 0; o < 8; ++o) { a1[o] = 0ull; a2[o] = 0ull; a3[o] = 0.f; }

        #pragma unroll
        for (int j = 0; j < 18; ++j) {
            const int row = r0 + j;
            ulonglong2 vq = s_q[row * IPQ + col];      // LDS.128
            float v3 = s_xy[row * IPQ + col];          // LDS.32
            #pragma unroll
            for (int o = 0; o < 8; ++o) {
                int k = j - o;
                if (k >= 0 && k < 11) {
                    u64 gk = pack2(G[k], G[k]);
                    a1[o] = fma2(vq.x, gk, a1[o]);
                    a2[o] = fma2(vq.y, gk, a2[o]);
                    a3[o] = fmaf(v3, G[k], a3[o]);
                }
            }
        }

        const float c1 = 1e-4f, c2 = 9e-4f;
        #pragma unroll
        for (int o = 0; o < 8; ++o) {
            float mu1, mu2, ex2, ey2;
            unpack2(a1[o], mu1, mu2);
            unpack2(a2[o], ex2, ey2);
            float mu1sq = mu1 * mu1;
            float mu2sq = mu2 * mu2;
            float mu12  = mu1 * mu2;
            float s1  = ex2 - mu1sq;
            float s2  = ey2 - mu2sq;
            float s12 = a3[o] - mu12;
            float num = (2.f * mu12 + c1) * (2.f * s12 + c2);
            float den = (mu1sq + mu2sq + c1) * (s1 + s2 + c2);
            lsum += __fdividef(num, den);
        }
    }

    // ---- Phase D: block reduce -> double atomic; last CTA finalizes ----
    #pragma unroll
    for (int off = 16; off; off >>= 1)
        lsum += __shfl_down_sync(0xffffffffu, lsum, off);
    __syncthreads();                       // smem reads done; reuse for reduce
    float* red = (float*)sm;
    if ((tid & 31) == 0) red[tid >> 5] = lsum;
    __syncthreads();
    if (tid == 0) {
        float bs = 0.f;
        #pragma unroll
        for (int i = 0; i < NT / 32; ++i) bs += red[i];
        atomicAdd(&g_accum, (double)bs);
        __threadfence();
        unsigned prev = atomicInc(&g_count, NBLOCKS - 1);  // wraps to 0 on last
        if (prev == NBLOCKS - 1) {
            double total = atomicAdd(&g_accum, 0.0);       // ordered read
            out[0] = (float)(total * (1.0 / ((double)NPLANE * W * H)));
            g_accum = 0.0;                                 // ready for next replay
        }
    }
}

extern "C" void kernel_launch(void* const* d_in, const int* in_sizes, int n_in,
                              void* d_out, int out_size) {
    const float* X = (const float*)d_in[0];
    const float* Y = (const float*)d_in[1];
    // d_in[2] (window) unused: taps fixed by problem definition, baked as constants.

    const int smem = HY * IPQ * 16 + HY * IPQ * 4;   // 48,840 B
    static int configured = 0;
    if (!configured) {
        cudaFuncSetAttribute(ssim_main, cudaFuncAttributeMaxDynamicSharedMemorySize, smem);
        configured = 1;
    }

    dim3 grid(W / TX, H / TY, NPLANE);
    ssim_main<<<grid, NT, smem>>>(X, Y, (float*)d_out);
}

// round 6
// speedup vs baseline: 1.2859x; 1.2859x over previous
#include <cuda_runtime.h>

#define W 512
#define H 512
#define NPLANE 48          // 16 batch * 3 channels
#define TX 32
#define TY 64
#define RAD 5
#define HC (TX + 2*RAD)    // 42 vertical-conv columns
#define PQ 43              // intermediate pitch (in ulonglong2 units / floats); odd -> conflict-free
#define NT 256             // 8 warps
#define NBLOCKS ((W/TX) * (H/TY) * NPLANE)   // 6144

typedef unsigned long long u64;

__device__ double   g_accum;   // zero at module load; reset by last CTA each call
__device__ unsigned g_count;   // auto-wrapping completion counter

__device__ __forceinline__ u64 pack2(float a, float b) {
    u64 r; asm("mov.b64 %0, {%1,%2};" : "=l"(r) : "f"(a), "f"(b)); return r;
}
__device__ __forceinline__ void unpack2(u64 v, float& a, float& b) {
    asm("mov.b64 {%0,%1}, %2;" : "=f"(a), "=f"(b) : "l"(v));
}
__device__ __forceinline__ u64 fma2(u64 a, u64 b, u64 c) {
    u64 d; asm("fma.rn.f32x2 %0, %1, %2, %3;" : "=l"(d) : "l"(a), "l"(b), "l"(c)); return d;
}
__device__ __forceinline__ u64 mul2(u64 a, u64 b) {
    u64 d; asm("mul.rn.f32x2 %0, %1, %2;" : "=l"(d) : "l"(a), "l"(b)); return d;
}

#define GDEF constexpr float G[11] = { \
    0.00102838f, 0.00759874f, 0.03600078f, 0.10936071f, 0.21300553f, \
    0.26601174f, \
    0.21300553f, 0.10936071f, 0.03600078f, 0.00759874f, 0.00102838f }

// Vertical 11-tap, 8-output strip for one column, streaming 18 gmem rows.
// Results go to smem planes at rows [s*8, s*8+8), column c.
template <bool CHK>
__device__ __forceinline__ void vtask(const float* __restrict__ Xp,
                                      const float* __restrict__ Yp,
                                      int gx, int gyBase, bool colOK,
                                      ulonglong2* __restrict__ s_q,
                                      float* __restrict__ s_xy,
                                      int c, int s) {
    GDEF;
    u64 a1[8], a2[8]; float a3[8];
    #pragma unroll
    for (int o = 0; o < 8; ++o) { a1[o] = 0ull; a2[o] = 0ull; a3[o] = 0.f; }

    #pragma unroll
    for (int j = 0; j < 18; ++j) {
        const int gy = gyBase + j;
        float xa = 0.f, ya = 0.f;
        if (!CHK || (colOK && (unsigned)gy < (unsigned)H)) {
            const int idx = gy * W + gx;
            xa = Xp[idx];
            ya = Yp[idx];
        }
        u64 v  = pack2(xa, ya);
        u64 v2 = mul2(v, v);
        float p = xa * ya;
        #pragma unroll
        for (int o = 0; o < 8; ++o) {
            int k = j - o;
            if (k >= 0 && k < 11) {
                u64 gk = pack2(G[k], G[k]);
                a1[o] = fma2(v,  gk, a1[o]);
                a2[o] = fma2(v2, gk, a2[o]);
                a3[o] = fmaf(p, G[k], a3[o]);
            }
        }
    }
    const int ryBase = s << 3;
    #pragma unroll
    for (int o = 0; o < 8; ++o) {
        s_q [(ryBase + o) * PQ + c] = make_ulonglong2(a1[o], a2[o]);
        s_xy[(ryBase + o) * PQ + c] = a3[o];
    }
}

__global__ __launch_bounds__(NT, 4) void ssim_main(const float* __restrict__ X,
                                                   const float* __restrict__ Y,
                                                   float* __restrict__ out) {
    extern __shared__ u64 sm[];
    ulonglong2* s_q  = (ulonglong2*)sm;          // [TY][PQ] (hx,hy),(hx2,hy2)
    float*      s_xy = (float*)(s_q + TY * PQ);  // [TY][PQ] hxy
    // total: 64*43*16 + 64*43*4 = 55,040 B

    const int tid = threadIdx.x;
    const int x0 = blockIdx.x * TX - RAD;        // leftmost v-column (gx)
    const int y0 = blockIdx.y * TY - RAD;        // topmost input row
    const float* Xp = X + (size_t)blockIdx.z * (W * H);
    const float* Yp = Y + (size_t)blockIdx.z * (W * H);

    const bool interior = (blockIdx.x > 0) & (blockIdx.x < W / TX - 1) &
                          (blockIdx.y > 0) & (blockIdx.y < H / TY - 1);

    // ---- Phase V: vertical conv straight from gmem (no halo in smem) ----
    // tasks (c in [0,42), s in [0,8)); round 1: 8 warps x 32 cols,
    // round 2: 80 leftover tasks (cols 32..41).
    if (interior) {
        if (tid < 80) {
            int c = 32 + tid % 10;
            int s = tid / 10;
            vtask<false>(Xp, Yp, x0 + c, y0 + s * 8, true, s_q, s_xy, c, s);
        }
        {
            int c = tid & 31;
            int s = tid >> 5;
            vtask<false>(Xp, Yp, x0 + c, y0 + s * 8, true, s_q, s_xy, c, s);
        }
    } else {
        if (tid < 80) {
            int c = 32 + tid % 10;
            int s = tid / 10;
            int gx = x0 + c;
            vtask<true>(Xp, Yp, gx, y0 + s * 8, (unsigned)gx < (unsigned)W,
                        s_q, s_xy, c, s);
        }
        {
            int c = tid & 31;
            int s = tid >> 5;
            int gx = x0 + c;
            vtask<true>(Xp, Yp, gx, y0 + s * 8, (unsigned)gx < (unsigned)W,
                        s_q, s_xy, c, s);
        }
    }
    __syncthreads();

    // ---- Phase H: horizontal conv + SSIM. 256 tasks = 64 rows x 4 strips ----
    // warp w: rows ((w&1)<<5)|lane, col strip c0 = (w>>1)*8.
    float lsum = 0.f;
    {
        GDEF;
        const int lane = tid & 31;
        const int w    = tid >> 5;
        const int r    = ((w & 1) << 5) | lane;
        const int c0   = (w >> 1) << 3;

        u64 a1[8], a2[8]; float a3[8];
        #pragma unroll
        for (int o = 0; o < 8; ++o) { a1[o] = 0ull; a2[o] = 0ull; a3[o] = 0.f; }

        #pragma unroll
        for (int j = 0; j < 18; ++j) {
            ulonglong2 vq = s_q [r * PQ + c0 + j];   // LDS.128, conflict-free
            float      v3 = s_xy[r * PQ + c0 + j];   // LDS.32, conflict-free
            #pragma unroll
            for (int o = 0; o < 8; ++o) {
                int k = j - o;
                if (k >= 0 && k < 11) {
                    u64 gk = pack2(G[k], G[k]);
                    a1[o] = fma2(vq.x, gk, a1[o]);
                    a2[o] = fma2(vq.y, gk, a2[o]);
                    a3[o] = fmaf(v3, G[k], a3[o]);
                }
            }
        }

        const float c1 = 1e-4f, c2 = 9e-4f;
        #pragma unroll
        for (int o = 0; o < 8; ++o) {
            float mu1, mu2, ex2, ey2;
            unpack2(a1[o], mu1, mu2);
            unpack2(a2[o], ex2, ey2);
            float mu1sq = mu1 * mu1;
            float mu2sq = mu2 * mu2;
            float mu12  = mu1 * mu2;
            float s1  = ex2 - mu1sq;
            float s2  = ey2 - mu2sq;
            float s12 = a3[o] - mu12;
            float num = (2.f * mu12 + c1) * (2.f * s12 + c2);
            float den = (mu1sq + mu2sq + c1) * (s1 + s2 + c2);
            lsum += __fdividef(num, den);
        }
    }

    // ---- Reduce -> double atomic; last CTA finalizes ----
    #pragma unroll
    for (int off = 16; off; off >>= 1)
        lsum += __shfl_down_sync(0xffffffffu, lsum, off);
    __syncthreads();                       // smem reads done; reuse for reduce
    float* red = (float*)sm;
    if ((tid & 31) == 0) red[tid >> 5] = lsum;
    __syncthreads();
    if (tid == 0) {
        float bs = 0.f;
        #pragma unroll
        for (int i = 0; i < NT / 32; ++i) bs += red[i];
        atomicAdd(&g_accum, (double)bs);
        __threadfence();
        unsigned prev = atomicInc(&g_count, NBLOCKS - 1);  // wraps to 0 on last
        if (prev == NBLOCKS - 1) {
            double total = atomicAdd(&g_accum, 0.0);       // ordered read
            out[0] = (float)(total * (1.0 / ((double)NPLANE * W * H)));
            g_accum = 0.0;                                 // ready for next replay
        }
    }
}

extern "C" void kernel_launch(void* const* d_in, const int* in_sizes, int n_in,
                              void* d_out, int out_size) {
    const float* X = (const float*)d_in[0];
    const float* Y = (const float*)d_in[1];
    // d_in[2] (window) unused: taps fixed by problem definition, baked as constants.

    const int smem = TY * PQ * 16 + TY * PQ * 4;   // 55,040 B
    static int configured = 0;
    if (!configured) {
        cudaFuncSetAttribute(ssim_main, cudaFuncAttributeMaxDynamicSharedMemorySize, smem);
        configured = 1;
    }

    dim3 grid(W / TX, H / TY, NPLANE);
    ssim_main<<<grid, NT, smem>>>(X, Y, (float*)d_out);
}

// round 7
// speedup vs baseline: 1.7898x; 1.3918x over previous
#include <cuda_runtime.h>

#define W 512
#define H 512
#define NPLANE 48          // 16 batch * 3 channels
#define TX 64
#define TY 32
#define RAD 5
#define VC (TX + 2*RAD)    // 74 vertical-conv columns
#define PQ 75              // intermediate pitch (odd -> conflict-free for lane=row reads)
#define NT 256             // 8 warps
#define NBLOCKS ((W/TX) * (H/TY) * NPLANE)   // 6144
#define NVT (VC * (TY/8)) // 296 vertical tasks

typedef unsigned long long u64;

__device__ double   g_accum;   // zero at module load; reset by last CTA each call
__device__ unsigned g_count;   // auto-wrapping completion counter

__device__ __forceinline__ u64 pack2(float a, float b) {
    u64 r; asm("mov.b64 %0, {%1,%2};" : "=l"(r) : "f"(a), "f"(b)); return r;
}
__device__ __forceinline__ void unpack2(u64 v, float& a, float& b) {
    asm("mov.b64 {%0,%1}, %2;" : "=f"(a), "=f"(b) : "l"(v));
}
__device__ __forceinline__ u64 fma2(u64 a, u64 b, u64 c) {
    u64 d; asm("fma.rn.f32x2 %0, %1, %2, %3;" : "=l"(d) : "l"(a), "l"(b), "l"(c)); return d;
}
__device__ __forceinline__ u64 mul2(u64 a, u64 b) {
    u64 d; asm("mul.rn.f32x2 %0, %1, %2;" : "=l"(d) : "l"(a), "l"(b)); return d;
}

#define GDEF constexpr float G[11] = { \
    0.00102838f, 0.00759874f, 0.03600078f, 0.10936071f, 0.21300553f, \
    0.26601174f, \
    0.21300553f, 0.10936071f, 0.03600078f, 0.00759874f, 0.00102838f }

// Vertical 11-tap, 8-output strip for one column, streaming 18 gmem rows.
template <bool CHK>
__device__ __forceinline__ void vtask(const float* __restrict__ Xp,
                                      const float* __restrict__ Yp,
                                      int gx, int gyBase, bool colOK,
                                      ulonglong2* __restrict__ s_q,
                                      float* __restrict__ s_xy,
                                      int c, int s) {
    GDEF;
    u64 a1[8], a2[8]; float a3[8];
    #pragma unroll
    for (int o = 0; o < 8; ++o) { a1[o] = 0ull; a2[o] = 0ull; a3[o] = 0.f; }

    #pragma unroll
    for (int j = 0; j < 18; ++j) {
        const int gy = gyBase + j;
        float xa = 0.f, ya = 0.f;
        if (!CHK || (colOK && (unsigned)gy < (unsigned)H)) {
            const int idx = gy * W + gx;
            xa = Xp[idx];
            ya = Yp[idx];
        }
        u64 v  = pack2(xa, ya);
        u64 v2 = mul2(v, v);
        float p = xa * ya;
        #pragma unroll
        for (int o = 0; o < 8; ++o) {
            int k = j - o;
            if (k >= 0 && k < 11) {
                u64 gk = pack2(G[k], G[k]);
                a1[o] = fma2(v,  gk, a1[o]);
                a2[o] = fma2(v2, gk, a2[o]);
                a3[o] = fmaf(p, G[k], a3[o]);
            }
        }
    }
    const int ryBase = s << 3;
    #pragma unroll
    for (int o = 0; o < 8; ++o) {
        s_q [(ryBase + o) * PQ + c] = make_ulonglong2(a1[o], a2[o]);
        s_xy[(ryBase + o) * PQ + c] = a3[o];
    }
}

__global__ __launch_bounds__(NT, 4) void ssim_main(const float* __restrict__ X,
                                                   const float* __restrict__ Y,
                                                   float* __restrict__ out) {
    extern __shared__ u64 sm[];
    ulonglong2* s_q  = (ulonglong2*)sm;          // [TY][PQ] (hx,hy),(hx2,hy2)
    float*      s_xy = (float*)(s_q + TY * PQ);  // [TY][PQ] hxy
    // total: 32*75*16 + 32*75*4 = 48,000 B

    const int tid = threadIdx.x;
    const int x0 = blockIdx.x * TX - RAD;        // leftmost v-column (gx)
    const int y0 = blockIdx.y * TY - RAD;        // topmost input row
    const float* Xp = X + (size_t)blockIdx.z * (W * H);
    const float* Yp = Y + (size_t)blockIdx.z * (W * H);

    const bool interior = (blockIdx.x > 0) & (blockIdx.x < W / TX - 1) &
                          (blockIdx.y > 0) & (blockIdx.y < H / TY - 1);

    // ---- Phase V: vertical conv straight from gmem ----
    // tasks t in [0,296): c = t % 74, strip s = t / 74.
    // round 1: tid (warp lanes -> consecutive cols, coalesced)
    // round 2: t2 = 256 + tid for tid < 40 -> s=3, c = 34 + tid
    if (interior) {
        if (tid < NVT - NT) {
            vtask<false>(Xp, Yp, x0 + 34 + tid, y0 + 24, true, s_q, s_xy,
                         34 + tid, 3);
        }
        {
            int s = tid / VC;
            int c = tid - s * VC;
            vtask<false>(Xp, Yp, x0 + c, y0 + s * 8, true, s_q, s_xy, c, s);
        }
    } else {
        if (tid < NVT - NT) {
            int c = 34 + tid;
            int gx = x0 + c;
            vtask<true>(Xp, Yp, gx, y0 + 24, (unsigned)gx < (unsigned)W,
                        s_q, s_xy, c, 3);
        }
        {
            int s = tid / VC;
            int c = tid - s * VC;
            int gx = x0 + c;
            vtask<true>(Xp, Yp, gx, y0 + s * 8, (unsigned)gx < (unsigned)W,
                        s_q, s_xy, c, s);
        }
    }
    __syncthreads();

    // ---- Phase H: horizontal conv + SSIM. 256 tasks = 32 rows x 8 strips ----
    // warp w: lane = row r, col strip c0 = w*8.  Conflict-free (pitch 75 odd).
    float lsum = 0.f;
    {
        GDEF;
        const int r  = tid & 31;
        const int c0 = (tid >> 5) << 3;

        u64 a1[8], a2[8]; float a3[8];
        #pragma unroll
        for (int o = 0; o < 8; ++o) { a1[o] = 0ull; a2[o] = 0ull; a3[o] = 0.f; }

        #pragma unroll
        for (int j = 0; j < 18; ++j) {
            ulonglong2 vq = s_q [r * PQ + c0 + j];   // LDS.128
            float      v3 = s_xy[r * PQ + c0 + j];   // LDS.32
            #pragma unroll
            for (int o = 0; o < 8; ++o) {
                int k = j - o;
                if (k >= 0 && k < 11) {
                    u64 gk = pack2(G[k], G[k]);
                    a1[o] = fma2(vq.x, gk, a1[o]);
                    a2[o] = fma2(vq.y, gk, a2[o]);
                    a3[o] = fmaf(v3, G[k], a3[o]);
                }
            }
        }

        const float c1 = 1e-4f, c2 = 9e-4f;
        #pragma unroll
        for (int o = 0; o < 8; ++o) {
            float mu1, mu2, ex2, ey2;
            unpack2(a1[o], mu1, mu2);
            unpack2(a2[o], ex2, ey2);
            float mu1sq = mu1 * mu1;
            float mu2sq = mu2 * mu2;
            float mu12  = mu1 * mu2;
            float s1  = ex2 - mu1sq;
            float s2  = ey2 - mu2sq;
            float s12 = a3[o] - mu12;
            float num = (2.f * mu12 + c1) * (2.f * s12 + c2);
            float den = (mu1sq + mu2sq + c1) * (s1 + s2 + c2);
            lsum += __fdividef(num, den);
        }
    }

    // ---- Reduce -> double atomic; last CTA finalizes ----
    #pragma unroll
    for (int off = 16; off; off >>= 1)
        lsum += __shfl_down_sync(0xffffffffu, lsum, off);
    __syncthreads();                       // smem reads done; reuse for reduce
    float* red = (float*)sm;
    if ((tid & 31) == 0) red[tid >> 5] = lsum;
    __syncthreads();
    if (tid == 0) {
        float bs = 0.f;
        #pragma unroll
        for (int i = 0; i < NT / 32; ++i) bs += red[i];
        atomicAdd(&g_accum, (double)bs);
        __threadfence();
        unsigned prev = atomicInc(&g_count, NBLOCKS - 1);  // wraps to 0 on last
        if (prev == NBLOCKS - 1) {
            double total = atomicAdd(&g_accum, 0.0);       // ordered read
            out[0] = (float)(total * (1.0 / ((double)NPLANE * W * H)));
            g_accum = 0.0;                                 // ready for next replay
        }
    }
}

extern "C" void kernel_launch(void* const* d_in, const int* in_sizes, int n_in,
                              void* d_out, int out_size) {
    const float* X = (const float*)d_in[0];
    const float* Y = (const float*)d_in[1];
    // d_in[2] (window) unused: taps fixed by problem definition, baked as constants.

    const int smem = TY * PQ * 16 + TY * PQ * 4;   // 48,000 B
    static int configured = 0;
    if (!configured) {
        cudaFuncSetAttribute(ssim_main, cudaFuncAttributeMaxDynamicSharedMemorySize, smem);
        configured = 1;
    }

    dim3 grid(W / TX, H / TY, NPLANE);
    ssim_main<<<grid, NT, smem>>>(X, Y, (float*)d_out);
}

// round 8
// speedup vs baseline: 2.0726x; 1.1581x over previous
#include <cuda_runtime.h>

#define W 512
#define H 512
#define NPLANE 48          // 16 batch * 3 channels
#define TX 64
#define TY 32
#define RAD 5
#define VC (TX + 2*RAD)    // 74 vertical-conv columns
#define PQ 75              // intermediate pitch (ulonglong2 units)
#define NT 256             // 8 warps
#define NBLOCKS ((W/TX) * (H/TY) * NPLANE)   // 6144
#define NVT (VC * (TY/8)) // 296 vertical tasks

typedef unsigned long long u64;

__device__ double   g_accum;   // zero at module load; reset by last CTA each call
__device__ unsigned g_count;   // auto-wrapping completion counter

__device__ __forceinline__ u64 pack2(float a, float b) {
    u64 r; asm("mov.b64 %0, {%1,%2};" : "=l"(r) : "f"(a), "f"(b)); return r;
}
__device__ __forceinline__ void unpack2(u64 v, float& a, float& b) {
    asm("mov.b64 {%0,%1}, %2;" : "=f"(a), "=f"(b) : "l"(v));
}
__device__ __forceinline__ u64 fma2(u64 a, u64 b, u64 c) {
    u64 d; asm("fma.rn.f32x2 %0, %1, %2, %3;" : "=l"(d) : "l"(a), "l"(b), "l"(c)); return d;
}
__device__ __forceinline__ u64 mul2(u64 a, u64 b) {
    u64 d; asm("mul.rn.f32x2 %0, %1, %2;" : "=l"(d) : "l"(a), "l"(b)); return d;
}

#define GDEF constexpr float G[11] = { \
    0.00102838f, 0.00759874f, 0.03600078f, 0.10936071f, 0.21300553f, \
    0.26601174f, \
    0.21300553f, 0.10936071f, 0.03600078f, 0.00759874f, 0.00102838f }

// Vertical 11-tap, 8-output strip for one column, streaming 18 gmem rows.
// Channels: pair1 = (x, y), pair2 = (s^2, d^2) with s=x+y, d=x-y.
template <bool CHK>
__device__ __forceinline__ void vtask(const float* __restrict__ Xp,
                                      const float* __restrict__ Yp,
                                      int gx, int gyBase, bool colOK,
                                      ulonglong2* __restrict__ s_q,
                                      int c, int s) {
    GDEF;
    u64 a1[8], a2[8];
    #pragma unroll
    for (int o = 0; o < 8; ++o) { a1[o] = 0ull; a2[o] = 0ull; }

    #pragma unroll
    for (int j = 0; j < 18; ++j) {
        const int gy = gyBase + j;
        float xa = 0.f, ya = 0.f;
        if (!CHK || (colOK && (unsigned)gy < (unsigned)H)) {
            const int idx = gy * W + gx;
            xa = Xp[idx];
            ya = Yp[idx];
        }
        u64 v   = pack2(xa, ya);
        u64 sd  = pack2(xa + ya, xa - ya);
        u64 sd2 = mul2(sd, sd);
        #pragma unroll
        for (int o = 0; o < 8; ++o) {
            int k = j - o;
            if (k >= 0 && k < 11) {
                u64 gk = pack2(G[k], G[k]);
                a1[o] = fma2(v,   gk, a1[o]);
                a2[o] = fma2(sd2, gk, a2[o]);
            }
        }
    }
    const int ryBase = s << 3;
    #pragma unroll
    for (int o = 0; o < 8; ++o)
        s_q[(ryBase + o) * PQ + c] = make_ulonglong2(a1[o], a2[o]);
}

__global__ __launch_bounds__(NT, 4) void ssim_main(const float* __restrict__ X,
                                                   const float* __restrict__ Y,
                                                   float* __restrict__ out) {
    extern __shared__ u64 sm[];
    ulonglong2* s_q = (ulonglong2*)sm;     // [TY][PQ]: (hx,hy),(hs2,hd2)
    // total: 32*75*16 = 38,400 B

    const int tid = threadIdx.x;
    const int x0 = blockIdx.x * TX - RAD;  // leftmost v-column (gx)
    const int y0 = blockIdx.y * TY - RAD;  // topmost input row
    const float* Xp = X + (size_t)blockIdx.z * (W * H);
    const float* Yp = Y + (size_t)blockIdx.z * (W * H);

    const bool interior = (blockIdx.x > 0) & (blockIdx.x < W / TX - 1) &
                          (blockIdx.y > 0) & (blockIdx.y < H / TY - 1);

    // ---- Phase V: vertical conv straight from gmem ----
    // round 1: t = tid (c = t % 74, s = t / 74); round 2: 40 leftovers (s=3)
    if (interior) {
        if (tid < NVT - NT)
            vtask<false>(Xp, Yp, x0 + 34 + tid, y0 + 24, true, s_q, 34 + tid, 3);
        {
            int s = tid / VC;
            int c = tid - s * VC;
            vtask<false>(Xp, Yp, x0 + c, y0 + s * 8, true, s_q, c, s);
        }
    } else {
        if (tid < NVT - NT) {
            int c = 34 + tid;
            int gx = x0 + c;
            vtask<true>(Xp, Yp, gx, y0 + 24, (unsigned)gx < (unsigned)W, s_q, c, 3);
        }
        {
            int s = tid / VC;
            int c = tid - s * VC;
            int gx = x0 + c;
            vtask<true>(Xp, Yp, gx, y0 + s * 8, (unsigned)gx < (unsigned)W, s_q, c, s);
        }
    }
    __syncthreads();

    // ---- Phase H: horizontal conv + SSIM. 256 tasks = 32 rows x 8 strips ----
    // warp w: lane = row r, col strip c0 = w*8. LDS.128, conflict-free per phase.
    float lsum = 0.f;
    {
        GDEF;
        const int r  = tid & 31;
        const int c0 = (tid >> 5) << 3;

        u64 a1[8], a2[8];
        #pragma unroll
        for (int o = 0; o < 8; ++o) { a1[o] = 0ull; a2[o] = 0ull; }

        #pragma unroll
        for (int j = 0; j < 18; ++j) {
            ulonglong2 vq = s_q[r * PQ + c0 + j];    // one LDS.128 per tap
            #pragma unroll
            for (int o = 0; o < 8; ++o) {
                int k = j - o;
                if (k >= 0 && k < 11) {
                    u64 gk = pack2(G[k], G[k]);
                    a1[o] = fma2(vq.x, gk, a1[o]);
                    a2[o] = fma2(vq.y, gk, a2[o]);
                }
            }
        }

        const float c1 = 1e-4f, c2 = 9e-4f;
        #pragma unroll
        for (int o = 0; o < 8; ++o) {
            float mu1, mu2, P, Q;
            unpack2(a1[o], mu1, mu2);
            unpack2(a2[o], P, Q);           // P = conv(s^2), Q = conv(d^2)
            float mu1sq = mu1 * mu1;
            float mu2sq = mu2 * mu2;
            float mu12  = mu1 * mu2;
            float sigsum = 0.5f  * (P + Q) - mu1sq - mu2sq;  // sigma1^2+sigma2^2
            float sig12  = 0.25f * (P - Q) - mu12;           // sigma12
            float num = (2.f * mu12 + c1) * (2.f * sig12 + c2);
            float den = (mu1sq + mu2sq + c1) * (sigsum + c2);
            lsum += __fdividef(num, den);
        }
    }

    // ---- Reduce -> double atomic; last CTA finalizes ----
    #pragma unroll
    for (int off = 16; off; off >>= 1)
        lsum += __shfl_down_sync(0xffffffffu, lsum, off);
    __syncthreads();                       // smem reads done; reuse for reduce
    float* red = (float*)sm;
    if ((tid & 31) == 0) red[tid >> 5] = lsum;
    __syncthreads();
    if (tid == 0) {
        float bs = 0.f;
        #pragma unroll
        for (int i = 0; i < NT / 32; ++i) bs += red[i];
        atomicAdd(&g_accum, (double)bs);
        __threadfence();
        unsigned prev = atomicInc(&g_count, NBLOCKS - 1);  // wraps to 0 on last
        if (prev == NBLOCKS - 1) {
            double total = atomicAdd(&g_accum, 0.0);       // ordered read
            out[0] = (float)(total * (1.0 / ((double)NPLANE * W * H)));
            g_accum = 0.0;                                 // ready for next replay
        }
    }
}

extern "C" void kernel_launch(void* const* d_in, const int* in_sizes, int n_in,
                              void* d_out, int out_size) {
    const float* X = (const float*)d_in[0];
    const float* Y = (const float*)d_in[1];
    // d_in[2] (window) unused: taps fixed by problem definition, baked as constants.

    const int smem = TY * PQ * 16;   // 38,400 B
    static int configured = 0;
    if (!configured) {
        cudaFuncSetAttribute(ssim_main, cudaFuncAttributeMaxDynamicSharedMemorySize, smem);
        configured = 1;
    }

    dim3 grid(W / TX, H / TY, NPLANE);
    ssim_main<<<grid, NT, smem>>>(X, Y, (float*)d_out);
}

// round 10
// speedup vs baseline: 2.0844x; 1.0057x over previous
#include <cuda_runtime.h>

#define W 512
#define H 512
#define NPLANE 48          // 16 batch * 3 channels
#define TX 128
#define TY 16
#define RAD 5
#define VC (TX + 2*RAD)    // 138 vertical-conv columns
#define PQ 139             // intermediate pitch in ulonglong2 units (odd)
#define NT 256             // 8 warps
#define NBLOCKS ((W/TX) * (H/TY) * NPLANE)   // 6144
#define NVT (VC * (TY/8))  // 276 vertical tasks

typedef unsigned long long u64;

__device__ double   g_accum;   // zero at module load; reset by last CTA each call
__device__ unsigned g_count;   // auto-wrapping completion counter

__device__ __forceinline__ u64 pack2(float a, float b) {
    u64 r; asm("mov.b64 %0, {%1,%2};" : "=l"(r) : "f"(a), "f"(b)); return r;
}
__device__ __forceinline__ void unpack2(u64 v, float& a, float& b) {
    asm("mov.b64 {%0,%1}, %2;" : "=f"(a), "=f"(b) : "l"(v));
}
__device__ __forceinline__ u64 fma2(u64 a, u64 b, u64 c) {
    u64 d; asm("fma.rn.f32x2 %0, %1, %2, %3;" : "=l"(d) : "l"(a), "l"(b), "l"(c)); return d;
}
__device__ __forceinline__ u64 mul2(u64 a, u64 b) {
    u64 d; asm("mul.rn.f32x2 %0, %1, %2;" : "=l"(d) : "l"(a), "l"(b)); return d;
}

#define GDEF constexpr float G[11] = { \
    0.00102838f, 0.00759874f, 0.03600078f, 0.10936071f, 0.21300553f, \
    0.26601174f, \
    0.21300553f, 0.10936071f, 0.03600078f, 0.00759874f, 0.00102838f }

// Vertical 11-tap, 8-output strip for one column, streaming 18 gmem rows.
// Channels: pair1 = (s, d) = (x+y, x-y);  pair2 = (s^2, d^2).
template <bool CHK>
__device__ __forceinline__ void vtask(const float* __restrict__ Xp,
                                      const float* __restrict__ Yp,
                                      int gx, int gyBase, bool colOK,
                                      ulonglong2* __restrict__ s_q,
                                      int c, int s) {
    GDEF;
    u64 a1[8], a2[8];
    #pragma unroll
    for (int o = 0; o < 8; ++o) { a1[o] = 0ull; a2[o] = 0ull; }

    #pragma unroll
    for (int j = 0; j < 18; ++j) {
        const int gy = gyBase + j;
        float xa = 0.f, ya = 0.f;
        if (!CHK || (colOK && (unsigned)gy < (unsigned)H)) {
            const int idx = gy * W + gx;
            xa = Xp[idx];
            ya = Yp[idx];
        }
        u64 v  = pack2(xa + ya, xa - ya);   // (s, d)
        u64 v2 = mul2(v, v);                // (s^2, d^2)
        #pragma unroll
        for (int o = 0; o < 8; ++o) {
            int k = j - o;
            if (k >= 0 && k < 11) {
                u64 gk = pack2(G[k], G[k]);
                a1[o] = fma2(v,  gk, a1[o]);
                a2[o] = fma2(v2, gk, a2[o]);
            }
        }
    }
    const int ryBase = s << 3;
    #pragma unroll
    for (int o = 0; o < 8; ++o)
        s_q[(ryBase + o) * PQ + c] = make_ulonglong2(a1[o], a2[o]);
}

__global__ __launch_bounds__(NT, 4) void ssim_main(const float* __restrict__ X,
                                                   const float* __restrict__ Y,
                                                   float* __restrict__ out) {
    extern __shared__ u64 sm[];
    ulonglong2* s_q = (ulonglong2*)sm;     // [TY][PQ]: (hs,hd),(hs2,hd2)
    // total: 16*139*16 = 35,584 B

    const int tid = threadIdx.x;
    const int x0 = blockIdx.x * TX - RAD;  // leftmost v-column (gx)
    const int y0 = blockIdx.y * TY - RAD;  // topmost input row
    const float* Xp = X + (size_t)blockIdx.z * (W * H);
    const float* Yp = Y + (size_t)blockIdx.z * (W * H);

    const bool interior = (blockIdx.x > 0) & (blockIdx.x < W / TX - 1) &
                          (blockIdx.y > 0) & (blockIdx.y < H / TY - 1);

    // ---- Phase V: vertical conv straight from gmem ----
    // tasks t in [0,276): c = t % 138, strip s = t / 138.
    // round 1: t = tid; round 2: 20 leftovers (s=1, c=118..137)
    if (interior) {
        if (tid < NVT - NT)
            vtask<false>(Xp, Yp, x0 + 118 + tid, y0 + 8, true, s_q, 118 + tid, 1);
        {
            int s = tid / VC;
            int c = tid - s * VC;
            vtask<false>(Xp, Yp, x0 + c, y0 + s * 8, true, s_q, c, s);
        }
    } else {
        if (tid < NVT - NT) {
            int c = 118 + tid;
            int gx = x0 + c;
            vtask<true>(Xp, Yp, gx, y0 + 8, (unsigned)gx < (unsigned)W, s_q, c, 1);
        }
        {
            int s = tid / VC;
            int c = tid - s * VC;
            int gx = x0 + c;
            vtask<true>(Xp, Yp, gx, y0 + s * 8, (unsigned)gx < (unsigned)W, s_q, c, s);
        }
    }
    __syncthreads();

    // ---- Phase H: horizontal conv + SSIM. 256 tasks = 16 rows x 16 strips ----
    float lsum = 0.f;
    {
        GDEF;
        const int r  = tid & 15;
        const int c0 = (tid >> 4) << 3;

        u64 a1[8], a2[8];
        #pragma unroll
        for (int o = 0; o < 8; ++o) { a1[o] = 0ull; a2[o] = 0ull; }

        #pragma unroll
        for (int j = 0; j < 18; ++j) {
            ulonglong2 vq = s_q[r * PQ + c0 + j];    // one LDS.128 per tap
            #pragma unroll
            for (int o = 0; o < 8; ++o) {
                int k = j - o;
                if (k >= 0 && k < 11) {
                    u64 gk = pack2(G[k], G[k]);
                    a1[o] = fma2(vq.x, gk, a1[o]);
                    a2[o] = fma2(vq.y, gk, a2[o]);
                }
            }
        }

        // Packed epilogue, two outputs at a time.
        // a1[o] = (ms, md) = (mu1+mu2, mu1-mu2); a2[o] = (P, Q) = E[s^2],E[d^2]
        // A = ms^2+md^2 = 2(mu1^2+mu2^2);  B = ms^2-md^2 = 4*mu1*mu2
        // num1 = B/2 + c1 = 2*mu12 + c1
        // num2 = (P-Q)/2 - B/2 + c2 = 2*sig12 + c2
        // den1 = A/2 + c1 = mu1^2+mu2^2 + c1
        // den2 = (P+Q)/2 - A/2 + c2 = sigsum + c2
        const u64 halfv  = pack2(0.5f, 0.5f);
        const u64 nhalfv = pack2(-0.5f, -0.5f);
        const u64 c1v    = pack2(1e-4f, 1e-4f);
        const u64 c2v    = pack2(9e-4f, 9e-4f);
        #pragma unroll
        for (int o = 0; o < 8; o += 2) {
            float ms2a, md2a, ms2b, md2b, Pa, Qa, Pb, Qb;
            unpack2(mul2(a1[o],     a1[o]),     ms2a, md2a);
            unpack2(mul2(a1[o + 1], a1[o + 1]), ms2b, md2b);
            unpack2(a2[o],     Pa, Qa);
            unpack2(a2[o + 1], Pb, Qb);
            u64 A  = pack2(ms2a + md2a, ms2b + md2b);
            u64 B  = pack2(ms2a - md2a, ms2b - md2b);
            u64 Ps = pack2(Pa + Qa, Pb + Qb);
            u64 Pd = pack2(Pa - Qa, Pb - Qb);
            u64 num1 = fma2(B, halfv, c1v);
            u64 num2 = fma2(Pd, halfv, fma2(B, nhalfv, c2v));
            u64 den1 = fma2(A, halfv, c1v);
            u64 den2 = fma2(Ps, halfv, fma2(A, nhalfv, c2v));
            float n0, n1, d0, d1;
            unpack2(mul2(num1, num2), n0, n1);
            unpack2(mul2(den1, den2), d0, d1);
            lsum += __fdividef(n0, d0);
            lsum += __fdividef(n1, d1);
        }
    }

    // ---- Reduce -> double atomic; last CTA finalizes ----
    #pragma unroll
    for (int off = 16; off; off >>= 1)
        lsum += __shfl_down_sync(0xffffffffu, lsum, off);
    __syncthreads();                       // smem reads done; reuse for reduce
    float* red = (float*)sm;
    if ((tid & 31) == 0) red[tid >> 5] = lsum;
    __syncthreads();
    if (tid == 0) {
        float bs = 0.f;
        #pragma unroll
        for (int i = 0; i < NT / 32; ++i) bs += red[i];
        atomicAdd(&g_accum, (double)bs);
        __threadfence();
        unsigned prev = atomicInc(&g_count, NBLOCKS - 1);  // wraps to 0 on last
        if (prev == NBLOCKS - 1) {
            double total = atomicAdd(&g_accum, 0.0);       // ordered read
            out[0] = (float)(total * (1.0 / ((double)NPLANE * W * H)));
            g_accum = 0.0;                                 // ready for next replay
        }
    }
}

extern "C" void kernel_launch(void* const* d_in, const int* in_sizes, int n_in,
                              void* d_out, int out_size) {
    const float* X = (const float*)d_in[0];
    const float* Y = (const float*)d_in[1];
    // d_in[2] (window) unused: taps fixed by problem definition, baked as constants.

    const int smem = TY * PQ * 16;   // 35,584 B
    static int configured = 0;
    if (!configured) {
        cudaFuncSetAttribute(ssim_main, cudaFuncAttributeMaxDynamicSharedMemorySize, smem);
        configured = 1;
    }

    dim3 grid(W / TX, H / TY, NPLANE);
    ssim_main<<<grid, NT, smem>>>(X, Y, (float*)d_out);
}